// round 15
// baseline (speedup 1.0000x reference)
#include <cuda_runtime.h>
#include <cuda_bf16.h>
#include <cuda_fp16.h>
#include <cstdint>
#include <cstddef>

#define D_MODEL 768
#define NHEAD   12
#define HEAD_DIM 64
#define BATCH   8
#define SEQ     1024
#define BH      (BATCH * NHEAD)     // 96
#define M_ROWS  (BATCH * SEQ)       // 8192
#define ADQ     128                 // fp16 attention dim: [q | k/48] vs [k' | pk]
#define INV_SCALE (1.0f / 48.0f)    // 1/sqrt(3*768)

// ---------------- scratch (static device allocation; no cudaMalloc) ----------------
__device__ float g_QKV [M_ROWS * 3 * D_MODEL];   // only k-part [768:1536) used now
__device__ float g_PQ  [M_ROWS * D_MODEL];

// attention operands (fp16)
__device__ __half g_Qc[(size_t)BH * SEQ * ADQ];      // [q | k/48]
__device__ __half g_Kc[(size_t)BH * SEQ * ADQ];      // [k' | pk]
__device__ __half g_Vt[(size_t)BH * HEAD_DIM * SEQ]; // transposed [bh][d][l]

// split-bf16 hi/lo planes for projections
__device__ __nv_bfloat16 g_xh [M_ROWS * D_MODEL];
__device__ __nv_bfloat16 g_xl [M_ROWS * D_MODEL];
__device__ __nv_bfloat16 g_ph [M_ROWS * D_MODEL];
__device__ __nv_bfloat16 g_pl [M_ROWS * D_MODEL];
__device__ __nv_bfloat16 g_wqh[3 * D_MODEL * D_MODEL];
__device__ __nv_bfloat16 g_wql[3 * D_MODEL * D_MODEL];
__device__ __nv_bfloat16 g_wpqh[D_MODEL * D_MODEL];
__device__ __nv_bfloat16 g_wpql[D_MODEL * D_MODEL];
__device__ __nv_bfloat16 g_wpkh[D_MODEL * D_MODEL];
__device__ __nv_bfloat16 g_wpkl[D_MODEL * D_MODEL];

// ==================== helpers ====================
__device__ __forceinline__ uint32_t smem_u32(const void* p) {
    uint32_t a;
    asm("{ .reg .u64 t; cvta.to.shared.u64 t, %1; cvt.u32.u64 %0, t; }" : "=r"(a) : "l"(p));
    return a;
}
__device__ __forceinline__ void cp16(uint32_t dst, const void* src) {
    asm volatile("cp.async.cg.shared.global [%0], [%1], 16;" :: "r"(dst), "l"(src));
}
__device__ __forceinline__ void cp_commit() {
    asm volatile("cp.async.commit_group;" ::: "memory");
}
template <int N>
__device__ __forceinline__ void cp_wait() {
    asm volatile("cp.async.wait_group %0;" :: "n"(N) : "memory");
}
__device__ __forceinline__ void ldm_x4(uint32_t& r0, uint32_t& r1, uint32_t& r2,
                                       uint32_t& r3, uint32_t addr) {
    asm volatile("ldmatrix.sync.aligned.m8n8.x4.shared.b16 {%0,%1,%2,%3}, [%4];"
                 : "=r"(r0), "=r"(r1), "=r"(r2), "=r"(r3) : "r"(addr));
}
__device__ __forceinline__ void mma16816(float* c, const uint32_t* a,
                                         uint32_t b0, uint32_t b1) {
    asm volatile(
        "mma.sync.aligned.m16n8k16.row.col.f32.bf16.bf16.f32 "
        "{%0,%1,%2,%3}, {%4,%5,%6,%7}, {%8,%9}, {%0,%1,%2,%3};"
        : "+f"(c[0]), "+f"(c[1]), "+f"(c[2]), "+f"(c[3])
        : "r"(a[0]), "r"(a[1]), "r"(a[2]), "r"(a[3]), "r"(b0), "r"(b1));
}
__device__ __forceinline__ void mma16816h(float* c, const uint32_t* a,
                                          uint32_t b0, uint32_t b1) {
    asm volatile(
        "mma.sync.aligned.m16n8k16.row.col.f32.f16.f16.f32 "
        "{%0,%1,%2,%3}, {%4,%5,%6,%7}, {%8,%9}, {%0,%1,%2,%3};"
        : "+f"(c[0]), "+f"(c[1]), "+f"(c[2]), "+f"(c[3])
        : "r"(a[0]), "r"(a[1]), "r"(a[2]), "r"(a[3]), "r"(b0), "r"(b1));
}
__device__ __forceinline__ uint32_t pack_h2(float lo, float hi) {
    __half2 h = __floats2half2_rn(lo, hi);
    return *(uint32_t*)&h;
}

// ==================== launch 1: fused split fp32 -> (hi, lo) bf16 planes ====================
#define NXE (M_ROWS * D_MODEL)
#define NWQE (3 * D_MODEL * D_MODEL)
#define NWE (D_MODEL * D_MODEL)
#define SPLIT_TOTAL (2 * NXE + NWQE + 2 * NWE)
#define SPLIT_V4 (SPLIT_TOTAL / 4)

__global__ __launch_bounds__(256) void split_all(
    const float* __restrict__ x, const float* __restrict__ pos,
    const float* __restrict__ wq, const float* __restrict__ wpq,
    const float* __restrict__ wpk)
{
    const int i4 = blockIdx.x * 256 + threadIdx.x;
    if (i4 >= SPLIT_V4) return;
    const int i = i4 * 4;
    const float* src;
    __nv_bfloat16 *hi, *lo;
    int j;
    if (i < NXE)                       { j = i;                        src = x;   hi = g_xh;   lo = g_xl;   }
    else if (i < 2 * NXE)              { j = i - NXE;                  src = pos; hi = g_ph;   lo = g_pl;   }
    else if (i < 2 * NXE + NWQE)       { j = i - 2 * NXE;              src = wq;  hi = g_wqh;  lo = g_wql;  }
    else if (i < 2 * NXE + NWQE + NWE) { j = i - 2 * NXE - NWQE;       src = wpq; hi = g_wpqh; lo = g_wpql; }
    else                               { j = i - 2 * NXE - NWQE - NWE; src = wpk; hi = g_wpkh; lo = g_wpkl; }

    const float4 v = *(const float4*)(src + j);
    union { __nv_bfloat162 h2[2]; uint2 u; } H, L;
    __nv_bfloat16 h0 = __float2bfloat16(v.x), h1 = __float2bfloat16(v.y);
    __nv_bfloat16 h2 = __float2bfloat16(v.z), h3 = __float2bfloat16(v.w);
    H.h2[0] = __nv_bfloat162(h0, h1);
    H.h2[1] = __nv_bfloat162(h2, h3);
    L.h2[0] = __nv_bfloat162(__float2bfloat16(v.x - __bfloat162float(h0)),
                             __float2bfloat16(v.y - __bfloat162float(h1)));
    L.h2[1] = __nv_bfloat162(__float2bfloat16(v.z - __bfloat162float(h2)),
                             __float2bfloat16(v.w - __bfloat162float(h3)));
    *(uint2*)(hi + j) = H.u;
    *(uint2*)(lo + j) = L.u;
}

// ==================== launches 2+3: split-bf16 GEMM, BK=48, fused epilogues =========
// mode = bx + bxoff:
//   0-5  (q):  fp16 q -> g_Qc[0..63]
//   6-11 (k):  fp32 k -> g_QKV AND fp16 k/48 -> g_Qc[64..127]
//   12-17(v):  fp16 -> g_Vt via smem-staged transpose (coalesced)
//   18-23(pq): fp32 -> g_PQ
//   24-29(pk): fp16 -> g_Kc[64..127]   (single-plane)
#define GK    768
#define GBK3  48
#define GP3   56                          // pitch (halves): 112B rows (16B-aligned, conflict-free)
#define PL3B  (128 * GP3 * 2)             // 14336 bytes per plane
#define OFF3_AH 0
#define OFF3_AL PL3B
#define OFF3_WH (2 * PL3B)
#define OFF3_WL (3 * PL3B)
#define GBUF3  (4 * PL3B)                 // 57344 per buffer
#define GSM3   (2 * GBUF3)                // 114688 -> 2 CTAs/SM (224KB <= 228KB)

__global__ __launch_bounds__(256, 2) void gemm128(
    const __nv_bfloat16* __restrict__ xh, const __nv_bfloat16* __restrict__ xl,
    const __nv_bfloat16* __restrict__ ph, const __nv_bfloat16* __restrict__ pl,
    const __nv_bfloat16* __restrict__ wqh, const __nv_bfloat16* __restrict__ wql,
    const __nv_bfloat16* __restrict__ wpqh, const __nv_bfloat16* __restrict__ wpql,
    const __nv_bfloat16* __restrict__ wpkh, const __nv_bfloat16* __restrict__ wpkl,
    const float* __restrict__ qkv_b, const float* __restrict__ pq_b,
    const float* __restrict__ pk_b, int bxoff)
{
    extern __shared__ char smg[];
    const uint32_t sbase = smem_u32(smg);
    const int tid = threadIdx.x, lane = tid & 31, wid = tid >> 5;
    const int wm = wid >> 1;
    const int wn = wid & 1;
    const int mode = blockIdx.x + bxoff;
    const int rowBase = blockIdx.y << 7;

    const __nv_bfloat16 *Ah, *Al, *Wh, *Wl;
    const float* bias;
    int colBase;
    bool three = true;
    if (mode < 18)      { Ah = xh; Al = xl; Wh = wqh;  Wl = wql;  bias = qkv_b; colBase = mode * 128; }
    else if (mode < 24) { Ah = ph; Al = pl; Wh = wpqh; Wl = wpql; bias = pq_b;  colBase = (mode - 18) * 128; }
    else                { Ah = ph; Al = pl; Wh = wpkh; Wl = wpkl; bias = pk_b;  colBase = (mode - 24) * 128; three = false; }

    const __nv_bfloat16* Ahg = Ah + (size_t)rowBase * GK;
    const __nv_bfloat16* Alg = Al + (size_t)rowBase * GK;
    const __nv_bfloat16* Whg = Wh + (size_t)colBase * GK;
    const __nv_bfloat16* Wlg = Wl + (size_t)colBase * GK;

    const uint32_t aoff = ((uint32_t)((wm * 32 + (lane & 15)) * GP3 + ((lane >> 4) * 8))) * 2;
    const uint32_t woff = ((uint32_t)((wn * 64 + ((lane >> 4) & 1) * 8 + (lane & 7)) * GP3
                                     + (((lane >> 3) & 1) * 8))) * 2;

    float c[2][8][4];
    #pragma unroll
    for (int i = 0; i < 2; i++)
        #pragma unroll
        for (int j = 0; j < 8; j++)
            #pragma unroll
            for (int k = 0; k < 4; k++) c[i][j][k] = 0.0f;

    auto load_chunk = [&](int ch, int buf) {
        const uint32_t base = sbase + (uint32_t)buf * GBUF3;
        const int k0 = ch * GBK3;
        #pragma unroll
        for (int it = 0; it < 3; it++) {          // 128 rows x 6 segs per plane
            const int idx = it * 256 + tid;       // 0..767
            const int row = idx / 6, seg = (idx % 6) * 8;
            const uint32_t so = (uint32_t)(row * GP3 + seg) * 2;
            const size_t go = (size_t)row * GK + k0 + seg;
            cp16(base + OFF3_AH + so, Ahg + go);
            cp16(base + OFF3_WH + so, Whg + go);
            if (three) {
                cp16(base + OFF3_AL + so, Alg + go);
                cp16(base + OFF3_WL + so, Wlg + go);
            }
        }
    };

    load_chunk(0, 0);
    cp_commit();

    const int NCH = GK / GBK3;   // 16
    for (int ch = 0; ch < NCH; ch++) {
        if (ch + 1 < NCH) {
            load_chunk(ch + 1, (ch + 1) & 1);
            cp_commit();
            cp_wait<1>();
        } else {
            cp_wait<0>();
        }
        __syncthreads();

        const uint32_t base = sbase + (uint32_t)(ch & 1) * GBUF3;
        #pragma unroll
        for (int kk = 0; kk < GBK3; kk += 16) {
            uint32_t ah[2][4], al[2][4];
            #pragma unroll
            for (int fa = 0; fa < 2; fa++) {
                ldm_x4(ah[fa][0], ah[fa][1], ah[fa][2], ah[fa][3],
                       base + OFF3_AH + aoff + (uint32_t)(fa * 16 * GP3 + kk) * 2);
                if (three)
                    ldm_x4(al[fa][0], al[fa][1], al[fa][2], al[fa][3],
                           base + OFF3_AL + aoff + (uint32_t)(fa * 16 * GP3 + kk) * 2);
            }
            #pragma unroll
            for (int fb = 0; fb < 4; fb++) {
                uint32_t b[4];
                ldm_x4(b[0], b[1], b[2], b[3],
                       base + OFF3_WH + woff + (uint32_t)(fb * 16 * GP3 + kk) * 2);
                #pragma unroll
                for (int fa = 0; fa < 2; fa++) {
                    mma16816(c[fa][fb * 2],     ah[fa], b[0], b[1]);
                    mma16816(c[fa][fb * 2 + 1], ah[fa], b[2], b[3]);
                    if (three) {
                        mma16816(c[fa][fb * 2],     al[fa], b[0], b[1]);
                        mma16816(c[fa][fb * 2 + 1], al[fa], b[2], b[3]);
                    }
                }
                if (three) {
                    ldm_x4(b[0], b[1], b[2], b[3],
                           base + OFF3_WL + woff + (uint32_t)(fb * 16 * GP3 + kk) * 2);
                    #pragma unroll
                    for (int fa = 0; fa < 2; fa++) {
                        mma16816(c[fa][fb * 2],     ah[fa], b[0], b[1]);
                        mma16816(c[fa][fb * 2 + 1], ah[fa], b[2], b[3]);
                    }
                }
            }
        }
        __syncthreads();
    }

    // ---- fused epilogue ----
    const int gq = lane >> 2, tq = lane & 3;

    if (mode >= 12 && mode < 18) {
        // ---- v: stage 128x128 fp16 tile in smem, then coalesced transposed writes ----
        __half* ts = (__half*)smg;                 // [128][130]
        #pragma unroll
        for (int fa = 0; fa < 2; fa++)
            #pragma unroll
            for (int nf = 0; nf < 8; nf++) {
                const int row0 = wm * 32 + fa * 16 + gq;     // local 0..127
                const int col = wn * 64 + nf * 8 + tq * 2;   // local, even
                const float b0 = bias[colBase + col], b1 = bias[colBase + col + 1];
                *(__half2*)&ts[row0 * 130 + col] =
                    __floats2half2_rn(c[fa][nf][0] + b0, c[fa][nf][1] + b1);
                *(__half2*)&ts[(row0 + 8) * 130 + col] =
                    __floats2half2_rn(c[fa][nf][2] + b0, c[fa][nf][3] + b1);
            }
        __syncthreads();
        {
            const int cl = tid >> 1;                   // local col 0..127
            const int lh = tid & 1;                    // which 64-row half
            const int ch = colBase + cl - 1536;
            const int h = ch >> 6, d = ch & 63;
            const int b_ = rowBase >> 10;
            const int lbase = (rowBase & (SEQ - 1)) + lh * 64;
            __half* dst = g_Vt + ((size_t)(b_ * NHEAD + h) * HEAD_DIM + d) * SEQ + lbase;
            #pragma unroll
            for (int j = 0; j < 64; j += 8) {
                union { __half h8[8]; uint4 u; } tmp;
                #pragma unroll
                for (int u = 0; u < 8; u++)
                    tmp.h8[u] = ts[(lh * 64 + j + u) * 130 + cl];
                *(uint4*)(dst + j) = tmp.u;
            }
        }
        return;
    }

    #pragma unroll
    for (int fa = 0; fa < 2; fa++) {
        #pragma unroll
        for (int nf = 0; nf < 8; nf++) {
            const int row0 = rowBase + wm * 32 + fa * 16 + gq;
            const int col = colBase + wn * 64 + nf * 8 + tq * 2;
            const float b0 = bias[col], b1 = bias[col + 1];
            const float v0a = c[fa][nf][0] + b0, v1a = c[fa][nf][1] + b1;
            const float v0b = c[fa][nf][2] + b0, v1b = c[fa][nf][3] + b1;

            if (mode < 6) {
                const int h = col >> 6, d = col & 63;
                #pragma unroll
                for (int rr = 0; rr < 2; rr++) {
                    const int row = row0 + rr * 8;
                    const float u0 = rr ? v0b : v0a, u1 = rr ? v1b : v1a;
                    const int b_ = row >> 10, l = row & (SEQ - 1);
                    const size_t baseQ = ((size_t)(b_ * NHEAD + h) * SEQ + l) * ADQ;
                    *(__half2*)&g_Qc[baseQ + d] = __floats2half2_rn(u0, u1);
                }
            } else if (mode < 12) {
                *(float2*)(g_QKV + (size_t)row0 * 2304 + col) = make_float2(v0a, v1a);
                *(float2*)(g_QKV + (size_t)(row0 + 8) * 2304 + col) = make_float2(v0b, v1b);
                const int ch = col - 768, h = ch >> 6, d = ch & 63;
                #pragma unroll
                for (int rr = 0; rr < 2; rr++) {
                    const int row = row0 + rr * 8;
                    const float u0 = rr ? v0b : v0a, u1 = rr ? v1b : v1a;
                    const int b_ = row >> 10, l = row & (SEQ - 1);
                    const size_t baseQ = ((size_t)(b_ * NHEAD + h) * SEQ + l) * ADQ;
                    *(__half2*)&g_Qc[baseQ + 64 + d] =
                        __floats2half2_rn(u0 * INV_SCALE, u1 * INV_SCALE);
                }
            } else if (mode < 24) {
                *(float2*)(g_PQ + (size_t)row0 * 768 + col) = make_float2(v0a, v1a);
                *(float2*)(g_PQ + (size_t)(row0 + 8) * 768 + col) = make_float2(v0b, v1b);
            } else {
                const int h = col >> 6, d = col & 63;
                #pragma unroll
                for (int rr = 0; rr < 2; rr++) {
                    const int row = row0 + rr * 8;
                    const float u0 = rr ? v0b : v0a, u1 = rr ? v1b : v1a;
                    const int b_ = row >> 10, l = row & (SEQ - 1);
                    const size_t baseK = ((size_t)(b_ * NHEAD + h) * SEQ + l) * ADQ;
                    *(__half2*)&g_Kc[baseK + 64 + d] = __floats2half2_rn(u0, u1);
                }
            }
        }
    }
}

// ==================== launch 4: build Kc[0..63] = fp16(k + pq) ====================
#define BQK_BLOCKS ((BH * SEQ * 64) / 256)

__global__ __launch_bounds__(256) void build_all()
{
    const int idx = blockIdx.x * 256 + threadIdx.x;
    const int d  = idx & 63;
    const int l  = (idx >> 6) & (SEQ - 1);
    const int bh = idx >> 16;
    const int b  = bh / NHEAD, h = bh - b * NHEAD;
    const size_t row = (size_t)b * SEQ + l;
    const int c = h * HEAD_DIM + d;
    const float k  = g_QKV[row * 2304 + 768 + c];
    const float pq = g_PQ[row * 768 + c];
    g_Kc[((size_t)bh * SEQ + l) * ADQ + d] = __float2half(k + pq);
}

// ==================== launch 5: fp16 flash attention (unchanged from R13) ==========
#define ABM 64
#define ABN 64
#define AQP 136
#define AVP 72
#define SK_OFF 0
#define SK_BYTES (ABN * AQP * 2)
#define SV_OFF (SK_OFF + 2 * SK_BYTES)
#define SV_BYTES (ABN * AVP * 2)
#define ASMEM (SV_OFF + 2 * SV_BYTES)    // 53248 -> 3 CTAs/SM

__global__ __launch_bounds__(128, 3) void attn_mma(float* __restrict__ out)
{
    extern __shared__ char smc[];
    const uint32_t sb = smem_u32(smc);
    const int tid = threadIdx.x, lane = tid & 31, w = tid >> 5;
    const int qb = blockIdx.x, bh = blockIdx.y;
    const int g = lane >> 2, t = lane & 3;

    const __half* Qg = g_Qc + ((size_t)bh * SEQ + (size_t)qb * ABM) * ADQ;
    const __half* Kg = g_Kc + (size_t)bh * SEQ * ADQ;
    const __half* Vg = g_Vt + (size_t)bh * HEAD_DIM * SEQ;

    const uint32_t aoff = (uint32_t)((w * 16 + (lane & 15)) * AQP + (lane >> 4) * 8) * 2;
    const uint32_t kfrag = (uint32_t)((((lane >> 4) & 1) * 8 + (lane & 7)) * AQP
                                     + ((lane >> 3) & 1) * 8) * 2;
    const uint32_t vfrag = (uint32_t)((((lane >> 4) & 1) * 8 + (lane & 7)) * AVP
                                     + ((lane >> 3) & 1) * 8) * 2;

    #pragma unroll
    for (int it = 0; it < 8; it++) {
        const int idx = it * 128 + tid;
        const int r = idx >> 4, s = idx & 15;
        cp16(sb + SK_OFF + (uint32_t)(r * AQP + s * 8) * 2, Qg + (size_t)r * ADQ + s * 8);
    }
    cp_commit();
    cp_wait<0>();
    __syncthreads();

    uint32_t qr[8][4];
    #pragma unroll
    for (int ks = 0; ks < ADQ / 16; ks++)
        ldm_x4(qr[ks][0], qr[ks][1], qr[ks][2], qr[ks][3],
               sb + SK_OFF + aoff + ks * 32);
    __syncthreads();

    auto loadKV = [&](int kt, int buf) {
        const __half* Kt = Kg + (size_t)kt * ABN * ADQ;
        #pragma unroll
        for (int it = 0; it < 8; it++) {
            const int idx = it * 128 + tid;
            const int r = idx >> 4, s = idx & 15;
            cp16(sb + SK_OFF + buf * SK_BYTES + (uint32_t)(r * AQP + s * 8) * 2,
                 Kt + (size_t)r * ADQ + s * 8);
        }
        #pragma unroll
        for (int it = 0; it < 4; it++) {
            const int idx = it * 128 + tid;
            const int r = idx >> 3, s = idx & 7;
            cp16(sb + SV_OFF + buf * SV_BYTES + (uint32_t)(r * AVP + s * 8) * 2,
                 Vg + (size_t)r * SEQ + kt * ABN + s * 8);
        }
    };
    loadKV(0, 0);
    cp_commit();

    float m0 = -1e30f, m1 = -1e30f, l0 = 0.0f, l1 = 0.0f;
    float o[8][4];
    #pragma unroll
    for (int f = 0; f < 8; f++)
        #pragma unroll
        for (int j = 0; j < 4; j++) o[f][j] = 0.0f;

    for (int kt = 0; kt < SEQ / ABN; kt++) {
        if (kt + 1 < SEQ / ABN) {
            loadKV(kt + 1, (kt + 1) & 1);
            cp_commit();
            cp_wait<1>();
        } else {
            cp_wait<0>();
        }
        __syncthreads();

        const uint32_t sK = sb + SK_OFF + (kt & 1) * SK_BYTES;
        const uint32_t sV = sb + SV_OFF + (kt & 1) * SV_BYTES;

        float c[8][4];
        #pragma unroll
        for (int f = 0; f < 8; f++)
            #pragma unroll
            for (int j = 0; j < 4; j++) c[f][j] = 0.0f;

        #pragma unroll
        for (int ks = 0; ks < ADQ / 16; ks++) {
            #pragma unroll
            for (int fb = 0; fb < 4; fb++) {
                uint32_t b[4];
                ldm_x4(b[0], b[1], b[2], b[3],
                       sK + kfrag + (uint32_t)(fb * 16 * AQP) * 2 + ks * 32);
                mma16816h(c[fb * 2],     qr[ks], b[0], b[1]);
                mma16816h(c[fb * 2 + 1], qr[ks], b[2], b[3]);
            }
        }

        float mx0 = c[0][0], mx1 = c[0][2];
        #pragma unroll
        for (int f = 0; f < 8; f++) {
            mx0 = fmaxf(mx0, fmaxf(c[f][0], c[f][1]));
            mx1 = fmaxf(mx1, fmaxf(c[f][2], c[f][3]));
        }
        mx0 = fmaxf(mx0, __shfl_xor_sync(0xffffffffu, mx0, 1));
        mx0 = fmaxf(mx0, __shfl_xor_sync(0xffffffffu, mx0, 2));
        mx1 = fmaxf(mx1, __shfl_xor_sync(0xffffffffu, mx1, 1));
        mx1 = fmaxf(mx1, __shfl_xor_sync(0xffffffffu, mx1, 2));
        const float nm0 = fmaxf(m0, mx0), nm1 = fmaxf(m1, mx1);
        const float cr0 = __expf(m0 - nm0), cr1 = __expf(m1 - nm1);
        m0 = nm0; m1 = nm1;
        float rs0 = 0.0f, rs1 = 0.0f;
        #pragma unroll
        for (int f = 0; f < 8; f++) {
            c[f][0] = __expf(c[f][0] - nm0); rs0 += c[f][0];
            c[f][1] = __expf(c[f][1] - nm0); rs0 += c[f][1];
            c[f][2] = __expf(c[f][2] - nm1); rs1 += c[f][2];
            c[f][3] = __expf(c[f][3] - nm1); rs1 += c[f][3];
        }
        l0 = l0 * cr0 + rs0;
        l1 = l1 * cr1 + rs1;
        #pragma unroll
        for (int f = 0; f < 8; f++) {
            o[f][0] *= cr0; o[f][1] *= cr0;
            o[f][2] *= cr1; o[f][3] *= cr1;
        }

        #pragma unroll
        for (int ks = 0; ks < ABN / 16; ks++) {
            uint32_t pa[4];
            pa[0] = pack_h2(c[2 * ks][0],     c[2 * ks][1]);
            pa[1] = pack_h2(c[2 * ks][2],     c[2 * ks][3]);
            pa[2] = pack_h2(c[2 * ks + 1][0], c[2 * ks + 1][1]);
            pa[3] = pack_h2(c[2 * ks + 1][2], c[2 * ks + 1][3]);
            #pragma unroll
            for (int fb = 0; fb < 4; fb++) {
                uint32_t vb[4];
                ldm_x4(vb[0], vb[1], vb[2], vb[3],
                       sV + vfrag + (uint32_t)(fb * 16 * AVP) * 2 + ks * 32);
                mma16816h(o[fb * 2],     pa, vb[0], vb[1]);
                mma16816h(o[fb * 2 + 1], pa, vb[2], vb[3]);
            }
        }
        __syncthreads();
    }

    l0 += __shfl_xor_sync(0xffffffffu, l0, 1);
    l0 += __shfl_xor_sync(0xffffffffu, l0, 2);
    l1 += __shfl_xor_sync(0xffffffffu, l1, 1);
    l1 += __shfl_xor_sync(0xffffffffu, l1, 2);
    const float inv0 = 1.0f / l0, inv1 = 1.0f / l1;
    const int b_ = bh / NHEAD, h = bh - b_ * NHEAD;
    const int r0 = qb * ABM + w * 16 + g;
    float* p0 = out + (((size_t)(b_ * SEQ + r0)) * NHEAD + h) * HEAD_DIM;
    float* p1 = out + (((size_t)(b_ * SEQ + r0 + 8)) * NHEAD + h) * HEAD_DIM;
    #pragma unroll
    for (int f = 0; f < 8; f++) {
        const int col = f * 8 + t * 2;
        *(float2*)(p0 + col) = make_float2(o[f][0] * inv0, o[f][1] * inv0);
        *(float2*)(p1 + col) = make_float2(o[f][2] * inv1, o[f][3] * inv1);
    }
}

// ====================================================================
extern "C" void kernel_launch(void* const* d_in, const int* in_sizes, int n_in,
                              void* d_out, int out_size)
{
    const float* x     = (const float*)d_in[0];
    const float* pos   = (const float*)d_in[1];
    const float* qkv_w = (const float*)d_in[2];
    const float* qkv_b = (const float*)d_in[3];
    const float* pq_w  = (const float*)d_in[4];
    const float* pq_b  = (const float*)d_in[5];
    const float* pk_w  = (const float*)d_in[6];
    const float* pk_b  = (const float*)d_in[7];
    float* out = (float*)d_out;

    __nv_bfloat16 *xh, *xl, *ph, *pl, *wqh, *wql, *wpqh, *wpql, *wpkh, *wpkl;
    cudaGetSymbolAddress((void**)&xh,   g_xh);
    cudaGetSymbolAddress((void**)&xl,   g_xl);
    cudaGetSymbolAddress((void**)&ph,   g_ph);
    cudaGetSymbolAddress((void**)&pl,   g_pl);
    cudaGetSymbolAddress((void**)&wqh,  g_wqh);
    cudaGetSymbolAddress((void**)&wql,  g_wql);
    cudaGetSymbolAddress((void**)&wpqh, g_wpqh);
    cudaGetSymbolAddress((void**)&wpql, g_wpql);
    cudaGetSymbolAddress((void**)&wpkh, g_wpkh);
    cudaGetSymbolAddress((void**)&wpkl, g_wpkl);

    // 1) split into hi/lo bf16 planes
    split_all<<<(SPLIT_V4 + 255) / 256, 256>>>(x, pos, qkv_w, pq_w, pk_w);

    // 2) qkv projection (q/k/v tiles)   3) pq+pk projections
    cudaFuncSetAttribute(gemm128, cudaFuncAttributeMaxDynamicSharedMemorySize, GSM3);
    gemm128<<<dim3(18, 64), 256, GSM3>>>(xh, xl, ph, pl, wqh, wql,
                                         wpqh, wpql, wpkh, wpkl,
                                         qkv_b, pq_b, pk_b, 0);
    gemm128<<<dim3(12, 64), 256, GSM3>>>(xh, xl, ph, pl, wqh, wql,
                                         wpqh, wpql, wpkh, wpkl,
                                         qkv_b, pq_b, pk_b, 18);

    // 4) build Kc[0..63] = fp16(k + pq)
    build_all<<<BQK_BLOCKS, 256>>>();

    // 5) fp16 flash attention
    cudaFuncSetAttribute(attn_mma, cudaFuncAttributeMaxDynamicSharedMemorySize, ASMEM);
    attn_mma<<<dim3(SEQ / ABM, BH), 128, ASMEM>>>(out);
}